// round 1
// baseline (speedup 1.0000x reference)
#include <cuda_runtime.h>
#include <cstdint>

// Problem dims (fixed by the dataset)
constexpr int NROWS = 16384;   // rows of x
constexpr int DK    = 2048;    // inner dim
constexpr int VCOLS = 8192;    // codebook size

// GEMM tiling
constexpr int BM = 128;
constexpr int BN = 128;
constexpr int BK = 16;
constexpr int TM = 8;
constexpr int TN = 8;
constexpr int NTHREADS = 256;  // 16x16 thread grid, each does TM x TN

// Global merge slots: (monotonic fp32 score << 32) | ~col  -> atomicMax picks
// max score; on equal score, larger ~col = SMALLER col wins (matches jnp.argmax
// first-occurrence tie-breaking).
__device__ unsigned long long g_best[NROWS];

__device__ __forceinline__ unsigned int enc_f32(float f) {
    unsigned int u = __float_as_uint(f);
    // monotonic mapping: order of encodings == order of floats
    return (u & 0x80000000u) ? ~u : (u | 0x80000000u);
}

__global__ void init_best_kernel() {
    int i = blockIdx.x * blockDim.x + threadIdx.x;
    if (i < NROWS) g_best[i] = 0ULL;  // any real score encodes > 0
}

__global__ __launch_bounds__(NTHREADS, 2)
void gemm_argmax_kernel(const float* __restrict__ x,
                        const float* __restrict__ di) {
    __shared__ float As[BK][BM];                 // 8 KB, transposed A tile
    __shared__ float Bs[BK][BN];                 // 8 KB
    __shared__ unsigned long long red[BM][16];   // 16 KB epilogue reduce

    const int tid = threadIdx.x;
    const int tx  = tid & 15;   // column group 0..15
    const int ty  = tid >> 4;   // row group 0..15
    const int rowBase = blockIdx.y * BM;
    const int colBase = blockIdx.x * BN;

    float acc[TM][TN];
#pragma unroll
    for (int i = 0; i < TM; i++)
#pragma unroll
        for (int j = 0; j < TN; j++) acc[i][j] = 0.0f;

    for (int k0 = 0; k0 < DK; k0 += BK) {
        // ---- load A tile: BM x BK = 2048 floats = 512 float4, 2 per thread
        // f -> row = f/4, kq = f%4 (each float4 = 4 consecutive k of one row)
#pragma unroll
        for (int i = 0; i < 2; i++) {
            int f   = tid + i * NTHREADS;
            int row = f >> 2;
            int kq  = (f & 3) << 2;
            const float4 v = *reinterpret_cast<const float4*>(
                &x[(size_t)(rowBase + row) * DK + k0 + kq]);
            As[kq + 0][row] = v.x;
            As[kq + 1][row] = v.y;
            As[kq + 2][row] = v.z;
            As[kq + 3][row] = v.w;
        }
        // ---- load B tile: BK x BN = 2048 floats, fully coalesced float4
#pragma unroll
        for (int i = 0; i < 2; i++) {
            int f    = tid + i * NTHREADS;
            int krow = f >> 5;
            int cq   = (f & 31) << 2;
            *reinterpret_cast<float4*>(&Bs[krow][cq]) =
                *reinterpret_cast<const float4*>(
                    &di[(size_t)(k0 + krow) * VCOLS + colBase + cq]);
        }
        __syncthreads();

#pragma unroll
        for (int k = 0; k < BK; k++) {
            float ra[TM], rb[TN];
            *reinterpret_cast<float4*>(&ra[0]) =
                *reinterpret_cast<const float4*>(&As[k][ty * TM]);
            *reinterpret_cast<float4*>(&ra[4]) =
                *reinterpret_cast<const float4*>(&As[k][ty * TM + 4]);
            *reinterpret_cast<float4*>(&rb[0]) =
                *reinterpret_cast<const float4*>(&Bs[k][tx * TN]);
            *reinterpret_cast<float4*>(&rb[4]) =
                *reinterpret_cast<const float4*>(&Bs[k][tx * TN + 4]);
#pragma unroll
            for (int i = 0; i < TM; i++)
#pragma unroll
                for (int j = 0; j < TN; j++)
                    acc[i][j] = fmaf(ra[i], rb[j], acc[i][j]);
        }
        __syncthreads();
    }

    // ---- epilogue: per-thread argmax over its TN columns, per row
#pragma unroll
    for (int i = 0; i < TM; i++) {
        float bestv = acc[i][0];
        int   bestj = 0;
#pragma unroll
        for (int j = 1; j < TN; j++) {
            // strict > keeps the LOWEST column on ties within the thread
            if (acc[i][j] > bestv) { bestv = acc[i][j]; bestj = j; }
        }
        unsigned int col = (unsigned int)(colBase + tx * TN + bestj);
        unsigned long long e =
            ((unsigned long long)enc_f32(bestv) << 32) | (unsigned int)(~col);
        red[ty * TM + i][tx] = e;
    }
    __syncthreads();

    // 128 threads reduce 16 partials per row, then merge globally
    if (tid < BM) {
        unsigned long long m = red[tid][0];
#pragma unroll
        for (int t = 1; t < 16; t++) {
            unsigned long long v = red[tid][t];
            if (v > m) m = v;
        }
        atomicMax(&g_best[rowBase + tid], m);
    }
}

__global__ void decode_kernel(float* __restrict__ out) {
    int i = blockIdx.x * blockDim.x + threadIdx.x;
    if (i < NROWS) {
        unsigned int col = ~(unsigned int)(g_best[i] & 0xFFFFFFFFu);
        out[i] = (float)col;
    }
}

extern "C" void kernel_launch(void* const* d_in, const int* in_sizes, int n_in,
                              void* d_out, int out_size) {
    const float* x  = (const float*)d_in[0];   // [N, D] fp32
    const float* di = (const float*)d_in[1];   // [D, V] fp32
    float* out = (float*)d_out;                // [N] fp32 (indices)

    init_best_kernel<<<(NROWS + 255) / 256, 256>>>();

    dim3 grid(VCOLS / BN, NROWS / BM);         // 64 x 128 = 8192 CTAs
    gemm_argmax_kernel<<<grid, NTHREADS>>>(x, di);

    decode_kernel<<<(NROWS + 255) / 256, 256>>>(out);
}

// round 2
// speedup vs baseline: 1.0002x; 1.0002x over previous
#include <cuda_runtime.h>
#include <cstdint>

// Problem dims (fixed by the dataset)
constexpr int NROWS = 16384;   // rows of x
constexpr int DK    = 2048;    // inner dim
constexpr int VCOLS = 8192;    // codebook size

// GEMM tiling
constexpr int BM = 128;
constexpr int BN = 128;
constexpr int BK = 16;
constexpr int TM = 8;
constexpr int TN = 8;
constexpr int NTHREADS = 256;  // 16x16 thread grid, each does TM x TN

// Global merge slots: (monotonic fp32 score << 32) | ~col  -> atomicMax picks
// max score; on equal score, larger ~col = SMALLER col wins (matches jnp.argmax
// first-occurrence tie-breaking).
__device__ unsigned long long g_best[NROWS];

__device__ __forceinline__ unsigned int enc_f32(float f) {
    unsigned int u = __float_as_uint(f);
    // monotonic mapping: order of encodings == order of floats
    return (u & 0x80000000u) ? ~u : (u | 0x80000000u);
}

__global__ void init_best_kernel() {
    int i = blockIdx.x * blockDim.x + threadIdx.x;
    if (i < NROWS) g_best[i] = 0ULL;  // any real score encodes > 0
}

__global__ __launch_bounds__(NTHREADS, 2)
void gemm_argmax_kernel(const float* __restrict__ x,
                        const float* __restrict__ di) {
    __shared__ float As[BK][BM];                 // 8 KB, transposed A tile
    __shared__ float Bs[BK][BN];                 // 8 KB
    __shared__ unsigned long long red[BM][16];   // 16 KB epilogue reduce

    const int tid = threadIdx.x;
    const int tx  = tid & 15;   // column group 0..15
    const int ty  = tid >> 4;   // row group 0..15
    const int rowBase = blockIdx.y * BM;
    const int colBase = blockIdx.x * BN;

    float acc[TM][TN];
#pragma unroll
    for (int i = 0; i < TM; i++)
#pragma unroll
        for (int j = 0; j < TN; j++) acc[i][j] = 0.0f;

    for (int k0 = 0; k0 < DK; k0 += BK) {
        // ---- load A tile: BM x BK = 2048 floats = 512 float4, 2 per thread
        // f -> row = f/4, kq = f%4 (each float4 = 4 consecutive k of one row)
#pragma unroll
        for (int i = 0; i < 2; i++) {
            int f   = tid + i * NTHREADS;
            int row = f >> 2;
            int kq  = (f & 3) << 2;
            const float4 v = *reinterpret_cast<const float4*>(
                &x[(size_t)(rowBase + row) * DK + k0 + kq]);
            As[kq + 0][row] = v.x;
            As[kq + 1][row] = v.y;
            As[kq + 2][row] = v.z;
            As[kq + 3][row] = v.w;
        }
        // ---- load B tile: BK x BN = 2048 floats, fully coalesced float4
#pragma unroll
        for (int i = 0; i < 2; i++) {
            int f    = tid + i * NTHREADS;
            int krow = f >> 5;
            int cq   = (f & 31) << 2;
            *reinterpret_cast<float4*>(&Bs[krow][cq]) =
                *reinterpret_cast<const float4*>(
                    &di[(size_t)(k0 + krow) * VCOLS + colBase + cq]);
        }
        __syncthreads();

#pragma unroll
        for (int k = 0; k < BK; k++) {
            float ra[TM], rb[TN];
            *reinterpret_cast<float4*>(&ra[0]) =
                *reinterpret_cast<const float4*>(&As[k][ty * TM]);
            *reinterpret_cast<float4*>(&ra[4]) =
                *reinterpret_cast<const float4*>(&As[k][ty * TM + 4]);
            *reinterpret_cast<float4*>(&rb[0]) =
                *reinterpret_cast<const float4*>(&Bs[k][tx * TN]);
            *reinterpret_cast<float4*>(&rb[4]) =
                *reinterpret_cast<const float4*>(&Bs[k][tx * TN + 4]);
#pragma unroll
            for (int i = 0; i < TM; i++)
#pragma unroll
                for (int j = 0; j < TN; j++)
                    acc[i][j] = fmaf(ra[i], rb[j], acc[i][j]);
        }
        __syncthreads();
    }

    // ---- epilogue: per-thread argmax over its TN columns, per row
#pragma unroll
    for (int i = 0; i < TM; i++) {
        float bestv = acc[i][0];
        int   bestj = 0;
#pragma unroll
        for (int j = 1; j < TN; j++) {
            // strict > keeps the LOWEST column on ties within the thread
            if (acc[i][j] > bestv) { bestv = acc[i][j]; bestj = j; }
        }
        unsigned int col = (unsigned int)(colBase + tx * TN + bestj);
        unsigned long long e =
            ((unsigned long long)enc_f32(bestv) << 32) | (unsigned int)(~col);
        red[ty * TM + i][tx] = e;
    }
    __syncthreads();

    // 128 threads reduce 16 partials per row, then merge globally
    if (tid < BM) {
        unsigned long long m = red[tid][0];
#pragma unroll
        for (int t = 1; t < 16; t++) {
            unsigned long long v = red[tid][t];
            if (v > m) m = v;
        }
        atomicMax(&g_best[rowBase + tid], m);
    }
}

__global__ void decode_kernel(float* __restrict__ out) {
    int i = blockIdx.x * blockDim.x + threadIdx.x;
    if (i < NROWS) {
        unsigned int col = ~(unsigned int)(g_best[i] & 0xFFFFFFFFu);
        out[i] = (float)col;
    }
}

extern "C" void kernel_launch(void* const* d_in, const int* in_sizes, int n_in,
                              void* d_out, int out_size) {
    const float* x  = (const float*)d_in[0];   // [N, D] fp32
    const float* di = (const float*)d_in[1];   // [D, V] fp32
    float* out = (float*)d_out;                // [N] fp32 (indices)

    init_best_kernel<<<(NROWS + 255) / 256, 256>>>();

    dim3 grid(VCOLS / BN, NROWS / BM);         // 64 x 128 = 8192 CTAs
    gemm_argmax_kernel<<<grid, NTHREADS>>>(x, di);

    decode_kernel<<<(NROWS + 255) / 256, 256>>>(out);
}